// round 8
// baseline (speedup 1.0000x reference)
#include <cuda_runtime.h>
#include <math.h>

#define BB 2
#define TT 1024
#define DD 128
#define HH 64
// DH = 2

// Scratch (allocation-free contract: __device__ globals)
__device__ float g_WT[4][DD * DD];          // transposed Wq, Wk, Wv, Wo
__device__ float g_Qh[BB * HH * TT * 2];    // Q head-major: [(b*64+h)*1024+t] float2
__device__ float g_KV[BB * HH * TT * 4];    // K/V interleaved: (k0,k1,v0,v1) per (b,h,t)
__device__ float g_AO[BB * TT * DD];        // attention out, row-major [t_glob][d]

__device__ __forceinline__ float ex2f(float x) {
    float y;
    asm("ex2.approx.ftz.f32 %0, %1;" : "=f"(y) : "f"(x));
    return y;
}

// packed f32x2 helpers (sm_103a FFMA2 — only reachable via PTX fma.rn.f32x2)
__device__ __forceinline__ void ffma2(unsigned long long& d,
                                      unsigned long long a,
                                      unsigned long long b) {
    asm("fma.rn.f32x2 %0, %1, %2, %0;" : "+l"(d) : "l"(a), "l"(b));
}
__device__ __forceinline__ unsigned long long pack2(float v) {
    unsigned long long r;
    asm("mov.b64 %0, {%1, %1};" : "=l"(r) : "f"(v));
    return r;
}
__device__ __forceinline__ float2 unpack2(unsigned long long v) {
    float2 f;
    asm("mov.b64 {%0, %1}, %2;" : "=f"(f.x), "=f"(f.y) : "l"(v));
    return f;
}

// ---------------------------------------------------------------------------
// Weight transpose: g_WT[z][k][j] = W_z[j][k], four 128x128 matrices.
// grid (4,4,4): z = matrix, (x,y) = 32x32 tile. block (32,8).
// ---------------------------------------------------------------------------
__global__ void __launch_bounds__(256) wtrans_kernel(const float* __restrict__ Wq,
                                                     const float* __restrict__ Wk,
                                                     const float* __restrict__ Wv,
                                                     const float* __restrict__ Wo) {
    __shared__ float t[32][33];
    const float* src = (blockIdx.z == 0) ? Wq : (blockIdx.z == 1) ? Wk
                     : (blockIdx.z == 2) ? Wv : Wo;
    float* dst = g_WT[blockIdx.z];
    const int row0 = blockIdx.x * 32;
    const int col0 = blockIdx.y * 32;
    const int tx = threadIdx.x, ty = threadIdx.y;

    #pragma unroll
    for (int i = 0; i < 4; i++)
        t[ty + 8 * i][tx] = src[(row0 + ty + 8 * i) * DD + col0 + tx];
    __syncthreads();
    #pragma unroll
    for (int i = 0; i < 4; i++)
        dst[(col0 + ty + 8 * i) * DD + row0 + tx] = t[tx][ty + 8 * i];
}

// ---------------------------------------------------------------------------
// GEMM core: 16 rows x 64 cols per block, full K=128 in one smem slab.
// 256 threads. Warp w covers rows 2w,2w+1 (half-warp picks the row);
// lane owns 4 consecutive cols. One barrier; inner loop is
// LDS.128 + broadcast LDS + mov.b64 + 2x fma.rn.f32x2 per k.
// Returns two packed f32x2 accumulators = cols (j..j+1), (j+2..j+3).
// ---------------------------------------------------------------------------
struct AccP { unsigned long long p0, p1; int r, jl; };

__device__ __forceinline__ AccP gemm16x64(const float* __restrict__ A,
                                          const float* __restrict__ WT,
                                          int row0, int col0,
                                          float sX[16][DD],
                                          float sW[DD][64]) {
    const int tid = threadIdx.x;
    const int warp = tid >> 5;
    const int lane = tid & 31;
    const int r = warp * 2 + (lane >> 4);        // 0..15
    const int jl = (lane & 15) * 4;              // 0..60

    // Stage 16 A rows (coalesced float4, 2 per thread)
    #pragma unroll
    for (int i = 0; i < 2; i++) {
        const int idx = tid + i * 256;           // 512 float4
        reinterpret_cast<float4*>(&sX[0][0])[idx] =
            reinterpret_cast<const float4*>(A + row0 * DD)[idx];
    }
    // Stage weight slab: WT[k][col0 + jj], 128 k x 64 cols = 2048 float4
    #pragma unroll
    for (int i = 0; i < 8; i++) {
        const int idx = tid + i * 256;
        const int k = idx >> 4;
        const int c4 = (idx & 15) * 4;
        *reinterpret_cast<float4*>(&sW[k][c4]) =
            *reinterpret_cast<const float4*>(WT + k * DD + col0 + c4);
    }
    __syncthreads();

    unsigned long long acc0 = 0ull, acc1 = 0ull;
    #pragma unroll 8
    for (int k = 0; k < DD; k++) {
        const unsigned long long ap = pack2(sX[r][k]);
        const ulonglong2 wv = *reinterpret_cast<const ulonglong2*>(&sW[k][jl]);
        ffma2(acc0, ap, wv.x);
        ffma2(acc1, ap, wv.y);
    }
    return AccP{acc0, acc1, r, jl};
}

// ---------------------------------------------------------------------------
// QKV projection: grid (128, 2, 3), 256 threads. z selects Q/K/V; y selects
// the 64-col half. Writes head-major Q / interleaved KV directly.
// ---------------------------------------------------------------------------
__global__ void __launch_bounds__(256) qkv_kernel(const float* __restrict__ x) {
    __shared__ float sX[16][DD];   // 8 KB
    __shared__ float sW[DD][64];   // 32 KB

    const int row0 = blockIdx.x * 16;
    const int col0 = blockIdx.y * 64;
    const int z = blockIdx.z;                 // 0=Q, 1=K, 2=V

    AccP acc = gemm16x64(x, g_WT[z], row0, col0, sX, sW);

    const float2 f0 = unpack2(acc.p0);        // cols j, j+1   -> head j/2
    const float2 f1 = unpack2(acc.p1);        // cols j+2, j+3 -> head j/2+1

    const int rg = row0 + acc.r;
    const int b = rg >> 10;
    const int t0 = rg & 1023;
    const int h0 = (col0 + acc.jl) >> 1;      // even
    const int i0 = (b * HH + h0) * TT + t0;
    const int i1 = (b * HH + h0 + 1) * TT + t0;

    if (z == 0) {
        float2* __restrict__ Qp = reinterpret_cast<float2*>(g_Qh);
        Qp[i0] = f0;
        Qp[i1] = f1;
    } else {
        const int off = (z == 1) ? 0 : 2;     // K -> .xy, V -> .zw
        float2* __restrict__ KVp = reinterpret_cast<float2*>(g_KV + off);
        KVp[i0 * 2] = f0;
        KVp[i1 * 2] = f1;
    }
}

// ---------------------------------------------------------------------------
// Causal attention, DH=2. One block per (b,h), 512 threads.
// Thread tid owns queries {tid, 1023-tid} (1025 keys -> balanced).
// Single-pass softmax (no max subtraction; scores bounded, rescale exact).
// K/V as one float4 per key in smem -> 1 broadcast LDS.128 per key.
// ---------------------------------------------------------------------------
__global__ void __launch_bounds__(512) attn_kernel() {
    __shared__ float4 sKV[TT];   // 16 KB

    const int tid = threadIdx.x;
    const int bh = blockIdx.x;                // b*64 + h
    const int b = bh >> 6;
    const int h = bh & 63;

    const float4* __restrict__ KVp = reinterpret_cast<const float4*>(g_KV) + bh * TT;
    const float2* __restrict__ Qp  = reinterpret_cast<const float2*>(g_Qh) + bh * TT;

    sKV[tid]       = KVp[tid];
    sKV[tid + 512] = KVp[tid + 512];
    __syncthreads();

    // fold 1/(sqrt(DH)*temperature) and log2(e) into the query
    const float cf = 1.4426950408889634f / (1.4142135623730951f * 0.8f);
    float2* __restrict__ Op = reinterpret_cast<float2*>(g_AO);

    #pragma unroll
    for (int qi = 0; qi < 2; qi++) {
        const int q = qi ? (TT - 1 - tid) : tid;
        const float2 qv = Qp[q];
        const float q0 = qv.x * cf;
        const float q1 = qv.y * cf;

        float l = 0.f, o0 = 0.f, o1 = 0.f;
        #pragma unroll 4
        for (int k = 0; k <= q; k++) {
            const float4 kv = sKV[k];
            const float s = fmaf(q1, kv.y, q0 * kv.x);
            const float p = ex2f(s);
            l += p;
            o0 = fmaf(p, kv.z, o0);
            o1 = fmaf(p, kv.w, o1);
        }
        const float inv = 1.0f / l;
        Op[(b * TT + q) * HH + h] = make_float2(o0 * inv, o1 * inv);
    }
}

// ---------------------------------------------------------------------------
// Output projection: out = AO @ Wo^T via g_WT[3]. grid (128, 2).
// ---------------------------------------------------------------------------
__global__ void __launch_bounds__(256) proj_kernel(float* __restrict__ out) {
    __shared__ float sX[16][DD];   // 8 KB
    __shared__ float sW[DD][64];   // 32 KB

    const int row0 = blockIdx.x * 16;
    const int col0 = blockIdx.y * 64;

    AccP acc = gemm16x64(g_AO, g_WT[3], row0, col0, sX, sW);

    const float2 f0 = unpack2(acc.p0);
    const float2 f1 = unpack2(acc.p1);
    const float4 o = make_float4(f0.x, f0.y, f1.x, f1.y);
    *reinterpret_cast<float4*>(out + (row0 + acc.r) * DD + col0 + acc.jl) = o;
}

extern "C" void kernel_launch(void* const* d_in, const int* in_sizes, int n_in,
                              void* d_out, int out_size) {
    const float* x  = (const float*)d_in[0];
    const float* Wq = (const float*)d_in[1];
    const float* Wk = (const float*)d_in[2];
    const float* Wv = (const float*)d_in[3];
    const float* Wo = (const float*)d_in[4];
    float* out = (float*)d_out;

    wtrans_kernel<<<dim3(4, 4, 4), dim3(32, 8)>>>(Wq, Wk, Wv, Wo);
    qkv_kernel<<<dim3(128, 2, 3), 256>>>(x);
    attn_kernel<<<BB * HH, 512>>>();
    proj_kernel<<<dim3(128, 2), 256>>>(out);
}

// round 9
// speedup vs baseline: 1.1854x; 1.1854x over previous
#include <cuda_runtime.h>
#include <math.h>

#define BB 2
#define TT 1024
#define DD 128
#define HH 64
// DH = 2

// Scratch (allocation-free contract: __device__ globals)
__device__ float g_WT[4][DD * DD];          // transposed Wq, Wk, Wv, Wo
__device__ float g_Qh[BB * HH * TT * 2];    // Q head-major: [(b*64+h)*1024+t] float2
__device__ float g_KV[BB * HH * TT * 4];    // (k0,k1,v0,v1) per (b,h,t)
__device__ float g_AO[BB * TT * DD];        // attention out, row-major [t_glob][d]

__device__ __forceinline__ float ex2f(float x) {
    float y;
    asm("ex2.approx.ftz.f32 %0, %1;" : "=f"(y) : "f"(x));
    return y;
}

// packed f32x2 helpers (sm_103a — only reachable via PTX)
__device__ __forceinline__ void ffma2(unsigned long long& d,
                                      unsigned long long a,
                                      unsigned long long b) {
    asm("fma.rn.f32x2 %0, %1, %2, %0;" : "+l"(d) : "l"(a), "l"(b));
}
__device__ __forceinline__ unsigned long long mul2(unsigned long long a,
                                                   unsigned long long b) {
    unsigned long long d;
    asm("mul.rn.f32x2 %0, %1, %2;" : "=l"(d) : "l"(a), "l"(b));
    return d;
}
__device__ __forceinline__ void fma2acc(unsigned long long& d,
                                        unsigned long long a,
                                        unsigned long long b,
                                        unsigned long long c) {
    asm("fma.rn.f32x2 %0, %1, %2, %3;" : "=l"(d) : "l"(a), "l"(b), "l"(c));
}
__device__ __forceinline__ void add2(unsigned long long& d, unsigned long long a) {
    asm("add.rn.f32x2 %0, %0, %1;" : "+l"(d) : "l"(a));
}
__device__ __forceinline__ unsigned long long pack2(float v) {
    unsigned long long r;
    asm("mov.b64 %0, {%1, %1};" : "=l"(r) : "f"(v));
    return r;
}
__device__ __forceinline__ unsigned long long packf2(float a, float b) {
    unsigned long long r;
    asm("mov.b64 %0, {%1, %2};" : "=l"(r) : "f"(a), "f"(b));
    return r;
}
__device__ __forceinline__ float2 unpack2(unsigned long long v) {
    float2 f;
    asm("mov.b64 {%0, %1}, %2;" : "=f"(f.x), "=f"(f.y) : "l"(v));
    return f;
}

// ---------------------------------------------------------------------------
// Weight transpose: g_WT[z][k][j] = W_z[j][k], four 128x128 matrices.
// ---------------------------------------------------------------------------
__global__ void __launch_bounds__(256) wtrans_kernel(const float* __restrict__ Wq,
                                                     const float* __restrict__ Wk,
                                                     const float* __restrict__ Wv,
                                                     const float* __restrict__ Wo) {
    __shared__ float t[32][33];
    const float* src = (blockIdx.z == 0) ? Wq : (blockIdx.z == 1) ? Wk
                     : (blockIdx.z == 2) ? Wv : Wo;
    float* dst = g_WT[blockIdx.z];
    const int row0 = blockIdx.x * 32;
    const int col0 = blockIdx.y * 32;
    const int tx = threadIdx.x, ty = threadIdx.y;

    #pragma unroll
    for (int i = 0; i < 4; i++)
        t[ty + 8 * i][tx] = src[(row0 + ty + 8 * i) * DD + col0 + tx];
    __syncthreads();
    #pragma unroll
    for (int i = 0; i < 4; i++)
        dst[(col0 + ty + 8 * i) * DD + row0 + tx] = t[tx][ty + 8 * i];
}

// ---------------------------------------------------------------------------
// GEMM core: 32 rows x 64 cols per block, full K=128 weight slab (one sync).
// 256 threads, 8 warps. Warp w -> rows 4w..4w+3 (4 rows/warp balances fma
// pipe vs smem crossbar); lane owns 2 consecutive cols (packed f32x2 accs).
// Inner loop per k: 1 LDS.64 (W pair) + 4 broadcast LDS + 4 pack + 4 FFMA2.
// ---------------------------------------------------------------------------
__device__ __forceinline__ void gemm32x64(const float* __restrict__ A,
                                          const float* __restrict__ WT,
                                          int row0, int col0,
                                          float sX[32][DD],
                                          float sW[DD][64],
                                          unsigned long long acc[4]) {
    const int tid = threadIdx.x;
    const int warp = tid >> 5;
    const int lane = tid & 31;

    // Stage 32 A rows: 1024 float4, coalesced
    #pragma unroll
    for (int i = 0; i < 4; i++) {
        const int idx = tid + i * 256;
        reinterpret_cast<float4*>(&sX[0][0])[idx] =
            reinterpret_cast<const float4*>(A + row0 * DD)[idx];
    }
    // Stage weight slab: WT[k][col0..col0+63], 2048 float4
    #pragma unroll
    for (int i = 0; i < 8; i++) {
        const int idx = tid + i * 256;
        const int k = idx >> 4;
        const int c4 = (idx & 15) * 4;
        *reinterpret_cast<float4*>(&sW[k][c4]) =
            *reinterpret_cast<const float4*>(WT + k * DD + col0 + c4);
    }
    __syncthreads();

    const int r0 = warp * 4;
    const int c2 = lane * 2;
    acc[0] = acc[1] = acc[2] = acc[3] = 0ull;

    #pragma unroll 8
    for (int k = 0; k < DD; k++) {
        const unsigned long long wv =
            *reinterpret_cast<const unsigned long long*>(&sW[k][c2]);
        ffma2(acc[0], pack2(sX[r0 + 0][k]), wv);
        ffma2(acc[1], pack2(sX[r0 + 1][k]), wv);
        ffma2(acc[2], pack2(sX[r0 + 2][k]), wv);
        ffma2(acc[3], pack2(sX[r0 + 3][k]), wv);
    }
}

// ---------------------------------------------------------------------------
// QKV projection: grid (64, 2, 3). Lane's col pair = one head's (d0,d1).
// ---------------------------------------------------------------------------
__global__ void __launch_bounds__(256) qkv_kernel(const float* __restrict__ x) {
    __shared__ float sX[32][DD];   // 16 KB
    __shared__ float sW[DD][64];   // 32 KB  (total 48 KB exactly)

    const int row0 = blockIdx.x * 32;
    const int col0 = blockIdx.y * 64;
    const int z = blockIdx.z;                 // 0=Q, 1=K, 2=V

    unsigned long long acc[4];
    gemm32x64(x, g_WT[z], row0, col0, sX, sW, acc);

    const int warp = threadIdx.x >> 5;
    const int lane = threadIdx.x & 31;
    const int h = (col0 >> 1) + lane;         // head index 0..63

    float2* __restrict__ Qp  = reinterpret_cast<float2*>(g_Qh);
    float2* __restrict__ KVp = reinterpret_cast<float2*>(g_KV);

    #pragma unroll
    for (int i = 0; i < 4; i++) {
        const int rg = row0 + warp * 4 + i;
        const int b = rg >> 10;
        const int t0 = rg & 1023;
        const int idx = (b * HH + h) * TT + t0;
        const float2 f = unpack2(acc[i]);
        if (z == 0)      Qp[idx] = f;
        else if (z == 1) KVp[idx * 2] = f;        // K -> .xy
        else             KVp[idx * 2 + 1] = f;    // V -> .zw
    }
}

// ---------------------------------------------------------------------------
// Causal attention, DH=2. One block per (b,h), 512 threads.
// Thread tid owns queries {tid, 1023-tid} (1025 keys -> balanced).
// Single-pass softmax (no max subtraction; scores bounded, rescale exact).
// Packed f32x2 inner loop: 2 keys per iter via pair-major K/V smem layout.
//   sKp[m] = (K0[2m], K0[2m+1], K1[2m], K1[2m+1]); sVp analogous.
// Per 2 keys: 2 LDS.128 + 5 f32x2-fma ops + 2 EX2 + 2 movs -> MUFU-bound.
// ---------------------------------------------------------------------------
__global__ void __launch_bounds__(512) attn_kernel() {
    __shared__ float4 sKp[TT / 2];   // 8 KB
    __shared__ float4 sVp[TT / 2];   // 8 KB

    const int tid = threadIdx.x;
    const int bh = blockIdx.x;                // b*64 + h
    const int b = bh >> 6;
    const int h = bh & 63;

    const float4* __restrict__ KVp = reinterpret_cast<const float4*>(g_KV) + bh * TT;
    const float2* __restrict__ Qp  = reinterpret_cast<const float2*>(g_Qh) + bh * TT;

    // Pair-major staging: thread handles key pair (2*tid, 2*tid+1)
    {
        const float4 a = KVp[2 * tid];
        const float4 c = KVp[2 * tid + 1];
        sKp[tid] = make_float4(a.x, c.x, a.y, c.y);
        sVp[tid] = make_float4(a.z, c.z, a.w, c.w);
    }
    __syncthreads();

    // fold 1/(sqrt(DH)*temperature) and log2(e) into the query
    const float cf = 1.4426950408889634f / (1.4142135623730951f * 0.8f);
    float2* __restrict__ Op = reinterpret_cast<float2*>(g_AO);

    #pragma unroll
    for (int qi = 0; qi < 2; qi++) {
        const int q = qi ? (TT - 1 - tid) : tid;
        const float2 qv = Qp[q];
        const float q0 = qv.x * cf;
        const float q1 = qv.y * cf;
        const unsigned long long q0p = pack2(q0);
        const unsigned long long q1p = pack2(q1);

        const int npairs = (q + 1) >> 1;
        unsigned long long lp = 0ull, o0p = 0ull, o1p = 0ull;

        #pragma unroll 2
        for (int m = 0; m < npairs; m++) {
            const ulonglong2 kk = *reinterpret_cast<const ulonglong2*>(&sKp[m]);
            unsigned long long s01;
            fma2acc(s01, q1p, kk.y, mul2(q0p, kk.x));
            const float2 s = unpack2(s01);
            const unsigned long long p01 = packf2(ex2f(s.x), ex2f(s.y));
            const ulonglong2 vv = *reinterpret_cast<const ulonglong2*>(&sVp[m]);
            add2(lp, p01);
            ffma2(o0p, p01, vv.x);
            ffma2(o1p, p01, vv.y);
        }

        const float2 lf = unpack2(lp);
        const float2 o0f = unpack2(o0p);
        const float2 o1f = unpack2(o1p);
        float l = lf.x + lf.y;
        float o0 = o0f.x + o0f.y;
        float o1 = o1f.x + o1f.y;

        if (((q + 1) & 1) != 0) {            // q even: scalar tail for key q
            const float4 kk = sKp[q >> 1];
            const float4 vv = sVp[q >> 1];
            const float s = fmaf(q1, kk.z, q0 * kk.x);
            const float p = ex2f(s);
            l += p;
            o0 = fmaf(p, vv.x, o0);
            o1 = fmaf(p, vv.z, o1);
        }

        const float inv = 1.0f / l;
        Op[(b * TT + q) * HH + h] = make_float2(o0 * inv, o1 * inv);
    }
}

// ---------------------------------------------------------------------------
// Output projection: out = AO @ Wo^T via g_WT[3]. grid (64, 2).
// ---------------------------------------------------------------------------
__global__ void __launch_bounds__(256) proj_kernel(float* __restrict__ out) {
    __shared__ float sX[32][DD];   // 16 KB
    __shared__ float sW[DD][64];   // 32 KB

    const int row0 = blockIdx.x * 32;
    const int col0 = blockIdx.y * 64;

    unsigned long long acc[4];
    gemm32x64(g_AO, g_WT[3], row0, col0, sX, sW, acc);

    const int warp = threadIdx.x >> 5;
    const int lane = threadIdx.x & 31;

    #pragma unroll
    for (int i = 0; i < 4; i++) {
        const int rg = row0 + warp * 4 + i;
        const float2 f = unpack2(acc[i]);
        *reinterpret_cast<float2*>(out + rg * DD + col0 + lane * 2) = f;
    }
}

extern "C" void kernel_launch(void* const* d_in, const int* in_sizes, int n_in,
                              void* d_out, int out_size) {
    const float* x  = (const float*)d_in[0];
    const float* Wq = (const float*)d_in[1];
    const float* Wk = (const float*)d_in[2];
    const float* Wv = (const float*)d_in[3];
    const float* Wo = (const float*)d_in[4];
    float* out = (float*)d_out;

    wtrans_kernel<<<dim3(4, 4, 4), dim3(32, 8)>>>(Wq, Wk, Wv, Wo);
    qkv_kernel<<<dim3(64, 2, 3), 256>>>(x);
    attn_kernel<<<BB * HH, 512>>>();
    proj_kernel<<<dim3(64, 2), 256>>>(out);
}